// round 9
// baseline (speedup 1.0000x reference)
#include <cuda_runtime.h>
#include <cstdint>

// ShadingLayer: out[b,c,h,w] = sum_k L[b,c,k] * H_k(n[b,:,h,w])
// R8 = R2 (2 float4-groups/thread, 6 front-batched LDG.128, streaming hints)
//      + packed f32x2 math (FFMA2 via PTX fma.rn.f32x2; pixel pairs are
//      register-adjacent inside each float4 so packing is free).
//
// d_in[0]: recnormalch fp32 (64,3,512,512)
// d_in[1]: fc_light    fp32 (64,27)
// d_out  : fp32 (64,3,512,512)

#define C1f 0.8862269254527580f
#define C2f 1.0233267079464885f
#define C3f 0.2477079561003757f
#define C4f 0.8580855308097834f
#define C5f 0.4290427654048917f

typedef unsigned long long u64;

static __device__ __forceinline__ float4 ldcs4(const float* p) {
    return __ldcs(reinterpret_cast<const float4*>(p));
}
static __device__ __forceinline__ void stcs4(float* p, float4 v) {
    __stcs(reinterpret_cast<float4*>(p), v);
}

// ---- packed f32x2 helpers ----
static __device__ __forceinline__ u64 pk2(float s) {           // (s, s)
    u64 d; asm("mov.b64 %0, {%1, %1};" : "=l"(d) : "f"(s)); return d;
}
static __device__ __forceinline__ u64 mul2(u64 a, u64 b) {
    u64 d; asm("mul.rn.f32x2 %0, %1, %2;" : "=l"(d) : "l"(a), "l"(b)); return d;
}
static __device__ __forceinline__ u64 add2(u64 a, u64 b) {
    u64 d; asm("add.rn.f32x2 %0, %1, %2;" : "=l"(d) : "l"(a), "l"(b)); return d;
}
static __device__ __forceinline__ u64 fma2(u64 a, u64 b, u64 c) {
    u64 d; asm("fma.rn.f32x2 %0, %1, %2, %3;" : "=l"(d) : "l"(a), "l"(b), "l"(c));
    return d;
}

__global__ __launch_bounds__(256)
void shading_kernel(const float* __restrict__ nrm,
                    const float* __restrict__ light,
                    float* __restrict__ out) {
    constexpr int HW = 512 * 512;          // pixels per plane
    const unsigned bid = blockIdx.x;
    const int b   = bid >> 7;              // batch
    const int blk = bid & 127;             // block within batch
    const int v0  = blk * 512 + threadIdx.x;

    // ---- front-batch all 6 data loads (MLP=6) ----
    const float* p0 = nrm + (size_t)b * 3 * HW + (size_t)v0 * 4;
    const float* p1 = p0 + 1024;           // +256 groups
    float4 X0 = ldcs4(p0);
    float4 Y0 = ldcs4(p0 + HW);
    float4 Z0 = ldcs4(p0 + 2 * HW);
    float4 X1 = ldcs4(p1);
    float4 Y1 = ldcs4(p1 + HW);
    float4 Z1 = ldcs4(p1 + 2 * HW);

    // ---- fold light coefficients (scalar, L2 broadcast) ----
    const float* Lb = light + b * 27;
    float a[3][9];
    #pragma unroll
    for (int c = 0; c < 3; c++) {
        a[c][0] = C1f * __ldg(Lb + 9 * c + 0);
        a[c][1] = C2f * __ldg(Lb + 9 * c + 1);
        a[c][2] = C2f * __ldg(Lb + 9 * c + 2);
        a[c][3] = C2f * __ldg(Lb + 9 * c + 3);
        a[c][4] = C3f * __ldg(Lb + 9 * c + 4);
        a[c][5] = C4f * __ldg(Lb + 9 * c + 5);
        a[c][6] = C4f * __ldg(Lb + 9 * c + 6);
        a[c][7] = C5f * __ldg(Lb + 9 * c + 7);
        a[c][8] = C4f * __ldg(Lb + 9 * c + 8);
    }

    const u64 TWO  = pk2(2.0f);
    const u64 NEG1 = pk2(-1.0f);

    float* q0 = out + (p0 - nrm);

    #pragma unroll
    for (int g = 0; g < 2; g++) {
        const float4 X = g ? X1 : X0;
        const float4 Y = g ? Y1 : Y0;
        const float4 Z = g ? Z1 : Z0;

        // pixel pairs: (p0,p1) and (p2,p3) are adjacent regs -> free pack
        const u64* Xq = reinterpret_cast<const u64*>(&X);
        const u64* Yq = reinterpret_cast<const u64*>(&Y);
        const u64* Zq = reinterpret_cast<const u64*>(&Z);

        u64 b5[2], b6[2], b7[2], b8[2], b9[2];
        #pragma unroll
        for (int p = 0; p < 2; p++) {
            const u64 xp = Xq[p], yp = Yq[p], zp = Zq[p];
            const u64 xx = mul2(xp, xp);
            const u64 yy = mul2(yp, yp);
            const u64 zz = mul2(zp, zp);
            b6[p] = mul2(xp, zp);
            b7[p] = mul2(yp, zp);
            b9[p] = mul2(xp, yp);
            b8[p] = fma2(yy, NEG1, xx);                     // xx - yy
            b5[p] = fma2(zz, TWO, mul2(add2(xx, yy), NEG1)); // 2zz - xx - yy
        }

        float4 o[3];
        #pragma unroll
        for (int c = 0; c < 3; c++) {
            // pack this channel's coefficients (rematerializable MOVs)
            const u64 k0 = pk2(a[c][0]);
            const u64 k1 = pk2(a[c][1]);
            const u64 k2 = pk2(a[c][2]);
            const u64 k3 = pk2(a[c][3]);
            const u64 k4 = pk2(a[c][4]);
            const u64 k5 = pk2(a[c][5]);
            const u64 k6 = pk2(a[c][6]);
            const u64 k7 = pk2(a[c][7]);
            const u64 k8 = pk2(a[c][8]);
            u64* oq = reinterpret_cast<u64*>(&o[c]);
            #pragma unroll
            for (int p = 0; p < 2; p++) {
                u64 r = k0;
                r = fma2(Zq[p], k1, r);
                r = fma2(Xq[p], k2, r);
                r = fma2(Yq[p], k3, r);
                r = fma2(b5[p], k4, r);
                r = fma2(b6[p], k5, r);
                r = fma2(b7[p], k6, r);
                r = fma2(b8[p], k7, r);
                r = fma2(b9[p], k8, r);
                oq[p] = r;
            }
        }

        float* q = g ? (q0 + 1024) : q0;
        stcs4(q,          o[0]);
        stcs4(q + HW,     o[1]);
        stcs4(q + 2 * HW, o[2]);
    }
}

extern "C" void kernel_launch(void* const* d_in, const int* in_sizes, int n_in,
                              void* d_out, int out_size) {
    const float* nrm   = (const float*)d_in[0];
    const float* light = (const float*)d_in[1];
    float* out = (float*)d_out;

    // 64 batches * 128 blocks = 8192 blocks, 256 threads, 2 groups/thread
    shading_kernel<<<8192, 256>>>(nrm, light, out);
}

// round 10
// speedup vs baseline: 1.0365x; 1.0365x over previous
#include <cuda_runtime.h>

// ShadingLayer: out[b,c,h,w] = sum_k L[b,c,k] * H_k(n[b,:,h,w])
// R9 = R2 champion (2 float4-groups/thread, 6 front-batched LDG.128,
//      streaming hints, per-thread reg-folded coefficients) with:
//      - block 512 (same 48 warps/SM; half the CTA boundaries/coeff bursts)
//      - store base derived from load pointer (single IADD chain)
//
// Series conclusion: DRAM ~6.05TB/s (77%) is the ceiling for this 1:1 R/W
// stream; outstanding-load capacity is register-file-conserved (~288 warps*MLP
// per SM). R2's balance (MLP=6 @ 40 regs) is optimal.
//
// d_in[0]: recnormalch fp32 (64,3,512,512)
// d_in[1]: fc_light    fp32 (64,27)
// d_out  : fp32 (64,3,512,512)

#define C1f 0.8862269254527580f
#define C2f 1.0233267079464885f
#define C3f 0.2477079561003757f
#define C4f 0.8580855308097834f
#define C5f 0.4290427654048917f

static __device__ __forceinline__ float4 ldcs4(const float* p) {
    return __ldcs(reinterpret_cast<const float4*>(p));
}
static __device__ __forceinline__ void stcs4(float* p, float4 v) {
    __stcs(reinterpret_cast<float4*>(p), v);
}

__global__ __launch_bounds__(512)
void shading_kernel(const float* __restrict__ nrm,
                    const float* __restrict__ light,
                    float* __restrict__ out) {
    constexpr int HW = 512 * 512;          // pixels per plane
    // 65536 float4-groups/plane; 1024 groups per block -> 64 blocks/batch
    const unsigned bid = blockIdx.x;
    const int b   = bid >> 6;              // batch
    const int blk = bid & 63;              // block within batch
    const int v0  = blk * 1024 + threadIdx.x;   // first float4-group
    // second group = v0 + 512 (coalesced across the block)

    // ---- front-batch all 6 data loads (MLP=6) ----
    const float* p0 = nrm + (size_t)b * 3 * HW + (size_t)v0 * 4;
    const float* p1 = p0 + 2048;           // +512 groups * 4 floats
    float4 X0 = ldcs4(p0);
    float4 Y0 = ldcs4(p0 + HW);
    float4 Z0 = ldcs4(p0 + 2 * HW);
    float4 X1 = ldcs4(p1);
    float4 Y1 = ldcs4(p1 + HW);
    float4 Z1 = ldcs4(p1 + 2 * HW);

    // ---- fold light coefficients (L2-broadcast hits, under load latency) ----
    const float* Lb = light + b * 27;
    float a[3][9];
    #pragma unroll
    for (int c = 0; c < 3; c++) {
        a[c][0] = C1f * __ldg(Lb + 9 * c + 0);
        a[c][1] = C2f * __ldg(Lb + 9 * c + 1);
        a[c][2] = C2f * __ldg(Lb + 9 * c + 2);
        a[c][3] = C2f * __ldg(Lb + 9 * c + 3);
        a[c][4] = C3f * __ldg(Lb + 9 * c + 4);
        a[c][5] = C4f * __ldg(Lb + 9 * c + 5);
        a[c][6] = C4f * __ldg(Lb + 9 * c + 6);
        a[c][7] = C5f * __ldg(Lb + 9 * c + 7);
        a[c][8] = C4f * __ldg(Lb + 9 * c + 8);
    }

    float* q0 = out + (p0 - nrm);          // store base from load base

    #pragma unroll
    for (int g = 0; g < 2; g++) {
        const float4 X = g ? X1 : X0;
        const float4 Y = g ? Y1 : Y0;
        const float4 Z = g ? Z1 : Z0;
        const float xs[4] = {X.x, X.y, X.z, X.w};
        const float ys[4] = {Y.x, Y.y, Y.z, Y.w};
        const float zs[4] = {Z.x, Z.y, Z.z, Z.w};
        float o[3][4];

        #pragma unroll
        for (int j = 0; j < 4; j++) {
            const float x = xs[j], y = ys[j], z = zs[j];
            const float xx = x * x;
            const float yy = y * y;
            const float b5 = 2.0f * z * z - xx - yy;
            const float b6 = x * z;
            const float b7 = y * z;
            const float b8 = xx - yy;
            const float b9 = x * y;
            #pragma unroll
            for (int c = 0; c < 3; c++) {
                float r = a[c][0];
                r = fmaf(a[c][1], z,  r);
                r = fmaf(a[c][2], x,  r);
                r = fmaf(a[c][3], y,  r);
                r = fmaf(a[c][4], b5, r);
                r = fmaf(a[c][5], b6, r);
                r = fmaf(a[c][6], b7, r);
                r = fmaf(a[c][7], b8, r);
                r = fmaf(a[c][8], b9, r);
                o[c][j] = r;
            }
        }

        float* q = g ? (q0 + 2048) : q0;
        stcs4(q,          make_float4(o[0][0], o[0][1], o[0][2], o[0][3]));
        stcs4(q + HW,     make_float4(o[1][0], o[1][1], o[1][2], o[1][3]));
        stcs4(q + 2 * HW, make_float4(o[2][0], o[2][1], o[2][2], o[2][3]));
    }
}

extern "C" void kernel_launch(void* const* d_in, const int* in_sizes, int n_in,
                              void* d_out, int out_size) {
    const float* nrm   = (const float*)d_in[0];
    const float* light = (const float*)d_in[1];
    float* out = (float*)d_out;

    // 64 batches * 64 blocks = 4096 blocks, 512 threads, 2 groups/thread
    shading_kernel<<<4096, 512>>>(nrm, light, out);
}